// round 11
// baseline (speedup 1.0000x reference)
#include <cuda_runtime.h>
#include <stdint.h>

#define BB   8
#define CC   11
#define HH   512
#define WWID 512
#define NIMG (BB*CC)        // 88
#define WPR  16             // 32-bit words per row (512/32)
#define WPI  (HH*WPR)       // words per image = 8192

#define EDGE_BLKS  2048
#define FLOOD_BASE 2048
#define LOSS_BASE  (FLOOD_BASE + NIMG)       // 2136
#define NLOSS1     512
#define TOTAL_BLKS (LOSS_BASE + NLOSS1)      // 2648
#define NQUADS     524288
#define QPB        5958                       // ceil(524288/88)

// scratch (static __device__ — no allocations)
__device__ uint32_t g_strong[NIMG*WPI];
__device__ uint32_t g_weak  [NIMG*WPI];
__device__ uint32_t g_dil   [NIMG*WPI];
__device__ float    g_t     [BB*HH*WWID];    // per-pixel w[g]*(vg-lse), 8MB
__device__ float    g_p1[NLOSS1];
__device__ float    g_p2[NIMG];
__device__ unsigned edge_done[BB];
__device__ unsigned lossmain_done = 0;
__device__ unsigned flood_done = 0;
__device__ unsigned le_count = 0;

__device__ __forceinline__ int reflectI(int r) {
    r = (r < 0) ? -r : r;
    return (r > HH-1) ? (2*(HH-1) - r) : r;
}

__device__ __forceinline__ float tf32r(float x) {
    uint32_t u = __float_as_uint(x);
    u += 0x1000u;
    u &= 0xFFFFE000u;
    return __uint_as_float(u);
}
__device__ __forceinline__ uint64_t tf32r2(uint64_t x) {
    uint32_t lo = (uint32_t)x, hi = (uint32_t)(x >> 32);
    lo = (lo + 0x1000u) & 0xFFFFE000u;
    hi = (hi + 0x1000u) & 0xFFFFE000u;
    return ((uint64_t)hi << 32) | lo;
}

__device__ __forceinline__ uint64_t fma2(uint64_t a, uint64_t b, uint64_t c) {
    uint64_t d; asm("fma.rn.f32x2 %0,%1,%2,%3;" : "=l"(d) : "l"(a), "l"(b), "l"(c)); return d;
}
__device__ __forceinline__ uint64_t mul2(uint64_t a, uint64_t b) {
    uint64_t d; asm("mul.rn.f32x2 %0,%1,%2;" : "=l"(d) : "l"(a), "l"(b)); return d;
}
__device__ __forceinline__ uint64_t add2(uint64_t a, uint64_t b) {
    uint64_t d; asm("add.rn.f32x2 %0,%1,%2;" : "=l"(d) : "l"(a), "l"(b)); return d;
}
__device__ __forceinline__ uint64_t sub2(uint64_t a, uint64_t b) {
    uint64_t d; asm("sub.rn.f32x2 %0,%1,%2;" : "=l"(d) : "l"(a), "l"(b)); return d;
}
__device__ __forceinline__ uint64_t pack2(float lo, float hi) {
    return ((uint64_t)__float_as_uint(hi) << 32) | (uint64_t)__float_as_uint(lo);
}

// shared overlay offsets in u64 units
#define O_PATT 0        // 1440
#define O_V    1440     // 1440
#define O_B    2880     // 1296
#define O_MAG  4176     // 1156
#define O_GT   5332     // 200 u64 = 1600 bytes
#define O_TOT  5532     // 44256 bytes

__global__ void __launch_bounds__(1024, 2) mega_kernel(
    const float* __restrict__ pd,
    const int*   __restrict__ gt,
    const float* __restrict__ weight,
    float* __restrict__ out)
{
    __shared__ __align__(16) uint64_t s_all[O_TOT];
    const int bid = blockIdx.x;
    const int tid = threadIdx.x;
    const int lane = tid & 31;

    // ======================================================================
    if (bid < EDGE_BLKS) {
        // ------------------------------ EDGES -------------------------------
        uint64_t* s_patt = s_all + O_PATT;
        uint64_t* s_v    = s_all + O_V;
        uint64_t* s_b    = s_all + O_B;
        uint64_t* s_mag  = s_all + O_MAG;
        uint8_t*  s_gt   = (uint8_t*)(s_all + O_GT);

        const int b  = bid >> 8;
        const int ey = (bid >> 4) & 15;
        const int ex = bid & 15;
        const int x0 = ex * 32;
        const int y0 = ey * 32;
        const bool interior = (ex != 0) && (ex != 15) && (ey != 0) && (ey != 15);

        const float G0 = tf32r(0.054488684549642945f);
        const float G1 = tf32r(0.244201342003233320f);
        const float G2 = tf32r(0.402619946894227900f);
        const uint64_t G0p = pack2(G0, G0), G1p = pack2(G1, G1), G2p = pack2(G2, G2);
        const uint64_t M2p = pack2(-2.f, -2.f), P2p = pack2(2.f, 2.f);
        const uint64_t Z2  = 0;
        const float TT = 0.41421356237309503f;

        float lutv;
        {
            float a0 = (float)( lane       & 1);
            float a1 = (float)((lane >> 1) & 1);
            float a2 = (float)((lane >> 2) & 1);
            float a3 = (float)((lane >> 3) & 1);
            float a4 = (float)((lane >> 4) & 1);
            float s = G0 * a0;
            s = fmaf(G1, a1, s);
            s = fmaf(G2, a2, s);
            s = fmaf(G1, a3, s);
            s = fmaf(G0, a4, s);
            lutv = tf32r(s);
        }

        for (int e = tid; e < 1600; e += 1024) {
            int i = e / 40, j = e - 40*i;
            s_gt[e] = (uint8_t)gt[(b << 18) + (reflectI(y0-4+i) << 9) + reflectI(x0-4+j)];
        }
        __syncthreads();

        for (int e = tid; e < 1440; e += 1024) {
            int i = e / 40, j = e - 40*i;
            uint64_t B = 0;
            #pragma unroll
            for (int k = 0; k < 5; k++) {
                int g = s_gt[(i+k)*40 + j];
                B |= 1ull << (5*g + k);
            }
            s_patt[e] = B;
        }
        __syncthreads();

        const uint64_t patt0 = s_patt[tid];
        const uint64_t pattX = (tid < 416) ? s_patt[tid + 1024] : 0;

        const int h_src0 = (tid / 36) * 40 + (tid % 36);
        const int h_srcX = ((tid + 1024) / 36) * 40 + ((tid + 1024) % 36);

        const int sb_i0 = tid / 34;
        const int sb_base0 = sb_i0*36 + (tid - 34*sb_i0) + 37;
        const int sb_iX = (tid + 1024) / 34;
        const int sb_baseX = sb_iX*36 + ((tid + 1024) - 34*sb_iX) + 37;

        auto sobel_math = [&](uint64_t b00, uint64_t b01, uint64_t b02,
                              uint64_t b10, uint64_t b12,
                              uint64_t b20, uint64_t b21, uint64_t b22) -> uint64_t {
            uint64_t gxp = sub2(Z2, b00);
            gxp = add2(gxp, b02);
            gxp = fma2(M2p, b10, gxp);
            gxp = fma2(P2p, b12, gxp);
            gxp = sub2(gxp, b20);
            gxp = add2(gxp, b22);
            uint64_t gyp = sub2(Z2, b00);
            gyp = fma2(M2p, b01, gyp);
            gyp = sub2(gyp, b02);
            gyp = add2(gyp, b20);
            gyp = fma2(P2p, b21, gyp);
            gyp = add2(gyp, b22);

            float gx0 = __uint_as_float((uint32_t)gxp);
            float gx1 = __uint_as_float((uint32_t)(gxp >> 32));
            float gy0 = __uint_as_float((uint32_t)gyp);
            float gy1 = __uint_as_float((uint32_t)(gyp >> 32));

            float s20 = __fadd_rn(__fadd_rn(__fmul_rn(gx0,gx0), __fmul_rn(gy0,gy0)), 1e-6f);
            float s21 = __fadd_rn(__fadd_rn(__fmul_rn(gx1,gx1), __fmul_rn(gy1,gy1)), 1e-6f);
            float m0 = sqrtf(s20);
            float m1 = sqrtf(s21);
            float ax0 = fabsf(gx0), ay0 = fabsf(gy0);
            float ax1 = fabsf(gx1), ay1 = fabsf(gy1);
            uint32_t d0 = (ay0 <= TT*ax0) ? 0u
                        : (ax0 <= TT*ay0) ? 1u
                        : (((gx0 > 0.f) == (gy0 > 0.f)) ? 2u : 3u);
            uint32_t d1 = (ay1 <= TT*ax1) ? 0u
                        : (ax1 <= TT*ay1) ? 1u
                        : (((gx1 > 0.f) == (gy1 > 0.f)) ? 2u : 3u);
            uint32_t mb0 = (__float_as_uint(m0) & ~3u) | d0;
            uint32_t mb1 = (__float_as_uint(m1) & ~3u) | d1;
            return ((uint64_t)mb1 << 32) | mb0;
        };

        auto sobel_fast = [&](int e, int base) {
            s_mag[e] = sobel_math(s_b[base-37], s_b[base-36], s_b[base-35],
                                  s_b[base-1],                s_b[base+1],
                                  s_b[base+35], s_b[base+36], s_b[base+37]);
        };
        auto hblur_do = [&](int e, int src) {
            const uint64_t* row = s_v + src;
            uint64_t s = mul2(G0p, row[0]);
            s = fma2(G1p, row[1], s);
            s = fma2(G2p, row[2], s);
            s = fma2(G1p, row[3], s);
            s = fma2(G0p, row[4], s);
            s_b[e] = tf32r2(s);
        };

        const int nw  = tid >> 5;          // warp = row (0..31)
        const int nmj = lane + 1;

        #pragma unroll 1
        for (int c2 = 0; c2 < 6; c2++) {
            const int sh0 = 10*c2, sh1 = sh0 + 5;

            {
                float v0 = __shfl_sync(0xffffffffu, lutv, (int)((patt0 >> sh0) & 31));
                float v1 = __shfl_sync(0xffffffffu, lutv, (int)((patt0 >> sh1) & 31));
                s_v[tid] = pack2(v0, v1);
                if (tid < 416) {           // warps 0..12 fully active
                    v0 = __shfl_sync(0xffffffffu, lutv, (int)((pattX >> sh0) & 31));
                    v1 = __shfl_sync(0xffffffffu, lutv, (int)((pattX >> sh1) & 31));
                    s_v[tid + 1024] = pack2(v0, v1);
                }
            }
            __syncthreads();

            hblur_do(tid, h_src0);
            if (tid < 272) hblur_do(tid + 1024, h_srcX);
            __syncthreads();

            if (interior) {
                sobel_fast(tid, sb_base0);
                if (tid < 132) sobel_fast(tid + 1024, sb_baseX);
            } else {
                for (int e = tid; e < 1156; e += 1024) {
                    int i = e / 34, j = e - 34*i;
                    int gy = y0 - 1 + i, gx = x0 - 1 + j;
                    uint64_t magp = 0;
                    if ((unsigned)gy < (unsigned)HH && (unsigned)gx < (unsigned)WWID) {
                        int am = (max(gy-1, 0)      - (y0 - 2)) * 36;
                        int a0 = (gy                - (y0 - 2)) * 36;
                        int ap = (min(gy+1, HH-1)   - (y0 - 2)) * 36;
                        int cm =  max(gx-1, 0)      - (x0 - 2);
                        int c0 =  gx                - (x0 - 2);
                        int cp =  min(gx+1, WWID-1) - (x0 - 2);
                        magp = sobel_math(s_b[am+cm], s_b[am+c0], s_b[am+cp],
                                          s_b[a0+cm],             s_b[a0+cp],
                                          s_b[ap+cm], s_b[ap+c0], s_b[ap+cp]);
                    }
                    s_mag[e] = magp;
                }
            }
            __syncthreads();

            {
                const float* magf = (const float*)s_mag;
                const int r  = nw;
                const int mi = r + 1;
                uint64_t mp = s_mag[mi*34 + nmj];
                unsigned sbits[2], wbits[2];
                #pragma unroll
                for (int l = 0; l < 2; l++) {
                    uint32_t mb = (uint32_t)(l ? (mp >> 32) : mp);
                    float m = __uint_as_float(mb);
                    int d = (int)(mb & 3u);
                    int dy = (d == 0) ? 0 : ((d == 2) ? -1 : 1);
                    int dx = (d == 1) ? 0 : 1;
                    float m1 = magf[((mi+dy)*34 + (nmj+dx))*2 + l];
                    float m2 = magf[((mi-dy)*34 + (nmj-dx))*2 + l];
                    float mr = tf32r(m);
                    int e2 = 0;
                    if (mr > tf32r(m1) && mr > tf32r(m2))
                        e2 = (m > 0.2f) ? 2 : ((m > 0.1f) ? 1 : 0);
                    sbits[l] = __ballot_sync(0xffffffffu, e2 == 2);
                    wbits[l] = __ballot_sync(0xffffffffu, e2 == 1);
                }
                if (lane == 0) {
                    int c = 2*c2;
                    int base0 = ((b*CC + c)*HH + y0 + r)*WPR + ex;
                    g_strong[base0] = sbits[0];
                    g_weak[base0]   = wbits[0];
                    if (c + 1 < CC) {
                        int base1 = base0 + HH*WPR;
                        g_strong[base1] = sbits[1];
                        g_weak[base1]   = wbits[1];
                    }
                }
            }
            __syncthreads();
        }

        __threadfence();
        __syncthreads();
        if (tid == 0) atomicAdd(&edge_done[b], 1u);
        return;
    }

    // ======================================================================
    if (bid >= LOSS_BASE) {
        // ---------------------------- LOSS-MAIN -----------------------------
        const int lbid = bid - LOSS_BASE;                // 0..511
        float acc = 0.f;
        #pragma unroll 1
        for (int it = 0; it < 4; it++) {
            int p  = lbid * 4096 + it * 1024 + tid;
            int b  = p >> 18;
            int hw = p & 262143;
            int g  = gt[p];
            const float* base = pd + (((size_t)b * CC) << 18) + hw;
            float vmax = -1e30f, vg = 0.f;
            float vals[CC];
            #pragma unroll
            for (int c = 0; c < CC; c++) {
                float v = base[(size_t)c << 18];
                vals[c] = v;
                if (c == g) vg = v;
                vmax = fmaxf(vmax, v);
            }
            float s = 0.f;
            #pragma unroll
            for (int c = 0; c < CC; c++) s += __expf(vals[c] - vmax);
            float lse = vmax + __logf(s);
            float t = weight[g] * (vg - lse);
            g_t[p] = t;
            acc += t;
        }
        #pragma unroll
        for (int off = 16; off > 0; off >>= 1)
            acc += __shfl_down_sync(0xffffffffu, acc, off);
        float* ws = (float*)s_all;
        if (lane == 0) ws[tid >> 5] = acc;
        __syncthreads();
        if (tid == 0) {
            float t = 0.f;
            #pragma unroll
            for (int i = 0; i < 32; i++) t += ws[i];
            g_p1[lbid] = t;
            __threadfence();
            atomicAdd(&lossmain_done, 1u);
        }
        return;
    }

    // ======================================================================
    // ------------------------------- FLOOD ---------------------------------
    {
        const int img = bid - FLOOD_BASE;                // 0..87
        const int bb  = img / CC;

        if (tid == 0) {
            while (atomicAdd(&edge_done[bb], 0u) < 256u) __nanosleep(64);
        }
        __syncthreads();

        uint32_t* sS = (uint32_t*)s_all;                 // 32KB overlay
        const uint32_t* gs = g_strong + (size_t)img * WPI;
        const uint32_t* gw = g_weak   + (size_t)img * WPI;

        const int col = tid & 15;
        const int r0  = (tid >> 4) * 8;
        const int ib  = r0 * WPR + col;

        uint32_t wreg[8];                                // owner-private weak bits
        #pragma unroll
        for (int k = 0; k < 8; k++) {
            int i = ib + k * WPR;
            uint32_t s = gs[i];
            sS[i] = s;
            wreg[k] = gw[i] & ~s;
        }
        __syncthreads();

        for (;;) {
            bool ch = false;
            #pragma unroll
            for (int pass = 0; pass < 2; pass++) {
                for (int kk = 0; kk < 8; kk++) {
                    int k = pass ? 7 - kk : kk;
                    uint32_t w = wreg[k];
                    if (!w) continue;
                    int r = r0 + k;
                    int i = r * WPR + col;
                    uint32_t ext = 0;
                    if (r > 0)     ext |= sS[i - WPR];
                    if (r < HH-1)  ext |= sS[i + WPR];
                    uint32_t side = 0;
                    if (col > 0) {
                        uint32_t lo = sS[i-1];
                        if (r > 0)    lo |= sS[i-1-WPR];
                        if (r < HH-1) lo |= sS[i-1+WPR];
                        side |= lo >> 31;
                    }
                    if (col < WPR-1) {
                        uint32_t hi = sS[i+1];
                        if (r > 0)    hi |= sS[i+1-WPR];
                        if (r < HH-1) hi |= sS[i+1+WPR];
                        side |= hi << 31;
                    }
                    uint32_t cur = sS[i];
                    bool lch = false;
                    for (;;) {
                        uint32_t o = cur | ext;
                        uint32_t d = o | (o << 1) | (o >> 1) | side;
                        uint32_t cand = d & w;
                        if (!cand) break;
                        cur |= cand; w &= ~cand; lch = true;
                    }
                    if (lch) { sS[i] = cur; wreg[k] = w; ch = true; }
                }
            }
            if (!__syncthreads_or((int)ch)) break;
        }

        uint32_t* gd = g_dil + (size_t)img * WPI;
        #pragma unroll
        for (int k = 0; k < 8; k++) {
            int r = r0 + k;
            int i = r * WPR + col;
            uint32_t s = sS[i];
            uint32_t d = s | (s << 1) | (s >> 1);
            if (r > 0)       d |= sS[i - WPR];
            if (r < HH-1)    d |= sS[i + WPR];
            if (col > 0)     d |= sS[i-1] >> 31;
            if (col < WPR-1) d |= sS[i+1] << 31;
            gd[i] = d;
        }

        __threadfence();
        __syncthreads();
        if (tid == 0) {
            atomicAdd(&flood_done, 1u);
            while (atomicAdd(&flood_done, 0u) < (unsigned)NIMG ||
                   atomicAdd(&lossmain_done, 0u) < (unsigned)NLOSS1)
                __nanosleep(64);
        }
        __syncthreads();

        // --------------------------- LOSS-EDGE ------------------------------
        const int q0   = img * QPB;
        const int qend = min(q0 + QPB, NQUADS);
        float s2 = 0.f;
        for (int q = q0 + tid; q < qend; q += 1024) {
            const int b  = q >> 16;
            const int hw = (q & 65535) << 2;
            const int widx = hw >> 5;
            const int4   g4 = ((const int4*)gt)[q];
            const float4 t4 = ((const float4*)g_t)[q];
            const int   gsx[4] = {g4.x, g4.y, g4.z, g4.w};
            const float tsx[4] = {t4.x, t4.y, t4.z, t4.w};
            #pragma unroll
            for (int j = 0; j < 4; j++) {
                uint32_t bits = g_dil[(size_t)(b * CC + gsx[j]) * WPI + widx];
                if ((bits >> ((hw + j) & 31)) & 1u) s2 += tsx[j];
            }
        }
        #pragma unroll
        for (int off = 16; off > 0; off >>= 1)
            s2 += __shfl_down_sync(0xffffffffu, s2, off);
        float* ws = (float*)s_all;
        if (lane == 0) ws[tid >> 5] = s2;
        __syncthreads();
        __shared__ bool isLast;
        if (tid == 0) {
            float t = 0.f;
            #pragma unroll
            for (int i = 0; i < 32; i++) t += ws[i];
            g_p2[img] = t;
            __threadfence();
            unsigned v = atomicAdd(&le_count, 1u);
            isLast = (v == NIMG - 1);
        }
        __syncthreads();

        if (isLast) {
            double a = 0.0;
            for (int i = tid; i < NLOSS1; i += 1024) a += (double)g_p1[i];
            for (int i = tid; i < NIMG;   i += 1024) a += 2.0 * (double)g_p2[i];
            #pragma unroll
            for (int off = 16; off > 0; off >>= 1)
                a += __shfl_down_sync(0xffffffffu, a, off);
            double* wd = (double*)s_all;
            if (lane == 0) wd[tid >> 5] = a;
            __syncthreads();
            if (tid == 0) {
                double t = 0.0;
                #pragma unroll
                for (int i = 0; i < 32; i++) t += wd[i];
                out[0] = (float)(-t / 2097152.0);
                // reset counters for next graph replay
                #pragma unroll
                for (int i = 0; i < BB; i++) edge_done[i] = 0;
                lossmain_done = 0;
                flood_done = 0;
                le_count = 0;
            }
        }
    }
}

// ---------------------------------------------------------------------------
extern "C" void kernel_launch(void* const* d_in, const int* in_sizes, int n_in,
                              void* d_out, int out_size)
{
    (void)in_sizes; (void)n_in; (void)out_size;
    const float* pd     = (const float*)d_in[0];
    const int*   gt     = (const int*)  d_in[1];
    const float* weight = (const float*)d_in[2];
    float* out = (float*)d_out;

    mega_kernel<<<TOTAL_BLKS, 1024>>>(pd, gt, weight, out);
}

// round 12
// speedup vs baseline: 1.1429x; 1.1429x over previous
#include <cuda_runtime.h>
#include <stdint.h>

#define BB   8
#define CC   11
#define HH   512
#define WWID 512
#define NIMG (BB*CC)        // 88
#define WPR  16             // 32-bit words per row (512/32)
#define WPI  (HH*WPR)       // words per image = 8192
#define NLOSS1 512
#define NLOSS2 2048

// scratch (static __device__ — no allocations)
__device__ uint32_t g_strong[NIMG*WPI];
__device__ uint32_t g_weak  [NIMG*WPI];
__device__ uint32_t g_dil   [NIMG*WPI];
__device__ float    g_t     [BB*HH*WWID];
__device__ float    g_p1[NLOSS1];
__device__ float    g_p2[NLOSS2];
__device__ unsigned g_count = 0;

__device__ __forceinline__ int reflectI(int r) {
    r = (r < 0) ? -r : r;
    return (r > HH-1) ? (2*(HH-1) - r) : r;
}

__device__ __forceinline__ float tf32r(float x) {
    uint32_t u = __float_as_uint(x);
    u += 0x1000u;
    u &= 0xFFFFE000u;
    return __uint_as_float(u);
}
__device__ __forceinline__ uint64_t tf32r2(uint64_t x) {
    uint32_t lo = (uint32_t)x, hi = (uint32_t)(x >> 32);
    lo = (lo + 0x1000u) & 0xFFFFE000u;
    hi = (hi + 0x1000u) & 0xFFFFE000u;
    return ((uint64_t)hi << 32) | lo;
}

__device__ __forceinline__ uint64_t fma2(uint64_t a, uint64_t b, uint64_t c) {
    uint64_t d; asm("fma.rn.f32x2 %0,%1,%2,%3;" : "=l"(d) : "l"(a), "l"(b), "l"(c)); return d;
}
__device__ __forceinline__ uint64_t mul2(uint64_t a, uint64_t b) {
    uint64_t d; asm("mul.rn.f32x2 %0,%1,%2;" : "=l"(d) : "l"(a), "l"(b)); return d;
}
__device__ __forceinline__ uint64_t add2(uint64_t a, uint64_t b) {
    uint64_t d; asm("add.rn.f32x2 %0,%1,%2;" : "=l"(d) : "l"(a), "l"(b)); return d;
}
__device__ __forceinline__ uint64_t sub2(uint64_t a, uint64_t b) {
    uint64_t d; asm("sub.rn.f32x2 %0,%1,%2;" : "=l"(d) : "l"(a), "l"(b)); return d;
}
__device__ __forceinline__ uint64_t pack2(float lo, float hi) {
    return ((uint64_t)__float_as_uint(hi) << 32) | (uint64_t)__float_as_uint(lo);
}

// ---------------------------------------------------------------------------
// Kernel 1: edges with 4-class passes (ulonglong2 = two f32x2 pairs).
// 3 passes over class quads {0-3},{4-7},{8-11(dummy)}.
// s_mag overlays s_v; s_patt (setup only) overlays s_b. 45.4KB static smem.
// Arithmetic chains bit-identical to R10.
// ---------------------------------------------------------------------------
__global__ void __launch_bounds__(512, 3) edges_kernel(const int* __restrict__ gt)
{
    __shared__ __align__(16) ulonglong2 s_v[1440];   // 23040 B; s_mag overlay
    __shared__ __align__(16) ulonglong2 s_b[1296];   // 20736 B; s_patt overlay
    __shared__ uint8_t s_gt[1600];

    ulonglong2* s_mag = s_v;                          // 1156 entries (34*34)
    uint64_t*   s_patt = (uint64_t*)s_b;              // 1440 entries (setup only)

    const int b    = blockIdx.z;
    const int x0   = blockIdx.x * 32;
    const int y0   = blockIdx.y * 32;
    const int tid  = threadIdx.x;
    const int lane = tid & 31;
    const bool interior = (blockIdx.x != 0) && (blockIdx.x != 15)
                       && (blockIdx.y != 0) && (blockIdx.y != 15);

    const float G0 = tf32r(0.054488684549642945f);
    const float G1 = tf32r(0.244201342003233320f);
    const float G2 = tf32r(0.402619946894227900f);
    const uint64_t G0p = pack2(G0, G0), G1p = pack2(G1, G1), G2p = pack2(G2, G2);
    const uint64_t M2p = pack2(-2.f, -2.f), P2p = pack2(2.f, 2.f);
    const uint64_t Z2  = 0;
    const float TT = 0.41421356237309503f;

    // 32-entry vblur LUT in a register (shfl lookup); exact R3 chain + tf32r.
    float lutv;
    {
        float a0 = (float)( lane       & 1);
        float a1 = (float)((lane >> 1) & 1);
        float a2 = (float)((lane >> 2) & 1);
        float a3 = (float)((lane >> 3) & 1);
        float a4 = (float)((lane >> 4) & 1);
        float s = G0 * a0;
        s = fmaf(G1, a1, s);
        s = fmaf(G2, a2, s);
        s = fmaf(G1, a3, s);
        s = fmaf(G0, a4, s);
        lutv = tf32r(s);
    }

    // gt halo (reflect)
    for (int e = tid; e < 1600; e += 512) {
        int i = e / 40, j = e - 40*i;
        s_gt[e] = (uint8_t)gt[(b << 18) + (reflectI(y0-4+i) << 9) + reflectI(x0-4+j)];
    }
    __syncthreads();

    // patterns into s_patt (s_b overlay), then cache per-thread in registers
    for (int e = tid; e < 1440; e += 512) {
        int i = e / 40, j = e - 40*i;
        uint64_t B = 0;
        #pragma unroll
        for (int k = 0; k < 5; k++) {
            int g = s_gt[(i+k)*40 + j];
            B |= 1ull << (5*g + k);
        }
        s_patt[e] = B;
    }
    __syncthreads();
    const uint64_t patt0 = s_patt[tid];
    const uint64_t patt1 = s_patt[tid + 512];
    const uint64_t patt2 = (tid < 416) ? s_patt[tid + 1024] : 0;
    // (reads complete before any s_b write: hblur writes come after the
    //  vblur barrier below)

    // hoisted hblur / sobel indices
    const int h_src0 = (tid / 36) * 40 + (tid % 36);
    const int h_src1 = ((tid + 512) / 36) * 40 + ((tid + 512) % 36);
    const int h_src2 = ((tid + 1024) / 36) * 40 + ((tid + 1024) % 36);
    const int sb_i0 = tid / 34;
    const int sb_base0 = sb_i0*36 + (tid - 34*sb_i0) + 37;
    const int sb_i1 = (tid + 512) / 34;
    const int sb_base1 = sb_i1*36 + ((tid + 512) - 34*sb_i1) + 37;
    const int sb_i2 = (tid + 1024) / 34;
    const int sb_base2 = sb_i2*36 + ((tid + 1024) - 34*sb_i2) + 37;

    // epilogue per pair: mag+dir packed (dir in 2 low mantissa bits)
    auto pair_epi = [&](uint64_t gxp, uint64_t gyp) -> uint64_t {
        float gx0 = __uint_as_float((uint32_t)gxp);
        float gx1 = __uint_as_float((uint32_t)(gxp >> 32));
        float gy0 = __uint_as_float((uint32_t)gyp);
        float gy1 = __uint_as_float((uint32_t)(gyp >> 32));
        float s20 = __fadd_rn(__fadd_rn(__fmul_rn(gx0,gx0), __fmul_rn(gy0,gy0)), 1e-6f);
        float s21 = __fadd_rn(__fadd_rn(__fmul_rn(gx1,gx1), __fmul_rn(gy1,gy1)), 1e-6f);
        float m0 = sqrtf(s20);
        float m1 = sqrtf(s21);
        float ax0 = fabsf(gx0), ay0 = fabsf(gy0);
        float ax1 = fabsf(gx1), ay1 = fabsf(gy1);
        uint32_t d0 = (ay0 <= TT*ax0) ? 0u
                    : (ax0 <= TT*ay0) ? 1u
                    : (((gx0 > 0.f) == (gy0 > 0.f)) ? 2u : 3u);
        uint32_t d1 = (ay1 <= TT*ax1) ? 0u
                    : (ax1 <= TT*ay1) ? 1u
                    : (((gx1 > 0.f) == (gy1 > 0.f)) ? 2u : 3u);
        uint32_t mb0 = (__float_as_uint(m0) & ~3u) | d0;
        uint32_t mb1 = (__float_as_uint(m1) & ~3u) | d1;
        return ((uint64_t)mb1 << 32) | mb0;
    };

    // 4-class sobel: incremental per-neighbor accumulation; each chain's
    // internal op order matches R10 exactly.
    auto sobel4 = [&](int am, int a0, int ap, int cm, int c0, int cp) -> ulonglong2 {
        uint64_t gxl, gyl, gxh, gyh;
        ulonglong2 t;
        t = s_b[am+cm];                                // b00: gx -, gy -
        gxl = sub2(Z2, t.x); gyl = sub2(Z2, t.x);
        gxh = sub2(Z2, t.y); gyh = sub2(Z2, t.y);
        t = s_b[am+c0];                                // b01: gy fma(-2)
        gyl = fma2(M2p, t.x, gyl); gyh = fma2(M2p, t.y, gyh);
        t = s_b[am+cp];                                // b02: gx +, gy -
        gxl = add2(gxl, t.x); gyl = sub2(gyl, t.x);
        gxh = add2(gxh, t.y); gyh = sub2(gyh, t.y);
        t = s_b[a0+cm];                                // b10: gx fma(-2)
        gxl = fma2(M2p, t.x, gxl); gxh = fma2(M2p, t.y, gxh);
        t = s_b[a0+cp];                                // b12: gx fma(+2)
        gxl = fma2(P2p, t.x, gxl); gxh = fma2(P2p, t.y, gxh);
        t = s_b[ap+cm];                                // b20: gx -, gy +
        gxl = sub2(gxl, t.x); gyl = add2(gyl, t.x);
        gxh = sub2(gxh, t.y); gyh = add2(gyh, t.y);
        t = s_b[ap+c0];                                // b21: gy fma(+2)
        gyl = fma2(P2p, t.x, gyl); gyh = fma2(P2p, t.y, gyh);
        t = s_b[ap+cp];                                // b22: gx +, gy +
        gxl = add2(gxl, t.x); gyl = add2(gyl, t.x);
        gxh = add2(gxh, t.y); gyh = add2(gyh, t.y);
        ulonglong2 r;
        r.x = pair_epi(gxl, gyl);
        r.y = pair_epi(gxh, gyh);
        return r;
    };

    auto sobel_fast = [&](int e, int base) {
        s_mag[e] = sobel4(base-37, base-1, base+35, 0, 1, 2);
    };
    auto hblur4 = [&](int e, int src) {
        const ulonglong2* row = s_v + src;
        ulonglong2 r0 = row[0], r1 = row[1], r2 = row[2], r3 = row[3], r4 = row[4];
        uint64_t sl = mul2(G0p, r0.x), sh = mul2(G0p, r0.y);
        sl = fma2(G1p, r1.x, sl); sh = fma2(G1p, r1.y, sh);
        sl = fma2(G2p, r2.x, sl); sh = fma2(G2p, r2.y, sh);
        sl = fma2(G1p, r3.x, sl); sh = fma2(G1p, r3.y, sh);
        sl = fma2(G0p, r4.x, sl); sh = fma2(G0p, r4.y, sh);
        ulonglong2 o; o.x = tf32r2(sl); o.y = tf32r2(sh);
        s_b[e] = o;
    };
    auto vblur4 = [&](int e, uint64_t B, int p) {
        int sh0 = 20*p;
        float v0 = __shfl_sync(0xffffffffu, lutv, (int)((B >> sh0) & 31));
        float v1 = __shfl_sync(0xffffffffu, lutv, (int)((B >> (sh0+5)) & 31));
        float v2 = __shfl_sync(0xffffffffu, lutv, (int)((B >> (sh0+10)) & 31));
        float v3 = __shfl_sync(0xffffffffu, lutv, (int)((B >> (sh0+15)) & 31));
        ulonglong2 o; o.x = pack2(v0, v1); o.y = pack2(v2, v3);
        s_v[e] = o;
    };

    const int nw  = tid >> 5;
    const int nmj = lane + 1;

    #pragma unroll 1
    for (int p = 0; p < 3; p++) {                  // class quad 4p..4p+3
        // vertical blur
        vblur4(tid,        patt0, p);
        vblur4(tid + 512,  patt1, p);
        if (tid < 416) vblur4(tid + 1024, patt2, p);   // warps 0..12 full
        __syncthreads();

        // horizontal blur
        hblur4(tid,       h_src0);
        hblur4(tid + 512, h_src1);
        if (tid < 272) hblur4(tid + 1024, h_src2);
        __syncthreads();

        // sobel
        if (interior) {
            sobel_fast(tid,       sb_base0);
            sobel_fast(tid + 512, sb_base1);
            if (tid < 132) sobel_fast(tid + 1024, sb_base2);
        } else {
            for (int e = tid; e < 1156; e += 512) {
                int i = e / 34, j = e - 34*i;
                int gy = y0 - 1 + i, gx = x0 - 1 + j;
                ulonglong2 magp; magp.x = 0; magp.y = 0;
                if ((unsigned)gy < (unsigned)HH && (unsigned)gx < (unsigned)WWID) {
                    int am = (max(gy-1, 0)      - (y0 - 2)) * 36;
                    int a0 = (gy                - (y0 - 2)) * 36;
                    int ap = (min(gy+1, HH-1)   - (y0 - 2)) * 36;
                    int cm =  max(gx-1, 0)      - (x0 - 2);
                    int c0 =  gx                - (x0 - 2);
                    int cp =  min(gx+1, WWID-1) - (x0 - 2);
                    magp = sobel4(am, a0, ap, cm, c0, cp);
                }
                s_mag[e] = magp;
            }
        }
        __syncthreads();

        // NMS + thresholds (2 rows/warp, 4 classes)
        {
            const float* magf = (const float*)s_mag;
            #pragma unroll
            for (int t = 0; t < 2; t++) {
                int r  = nw + t*16;
                int mi = r + 1;
                ulonglong2 mp = s_mag[mi*34 + nmj];
                uint32_t mw[4] = {(uint32_t)mp.x, (uint32_t)(mp.x >> 32),
                                  (uint32_t)mp.y, (uint32_t)(mp.y >> 32)};
                unsigned sbits[4], wbits[4];
                #pragma unroll
                for (int l = 0; l < 4; l++) {
                    uint32_t mb = mw[l];
                    float m = __uint_as_float(mb);
                    int d = (int)(mb & 3u);
                    int dy = (d == 0) ? 0 : ((d == 2) ? -1 : 1);
                    int dx = (d == 1) ? 0 : 1;
                    float m1 = magf[((mi+dy)*34 + (nmj+dx))*4 + l];
                    float m2 = magf[((mi-dy)*34 + (nmj-dx))*4 + l];
                    float mr = tf32r(m);
                    int e2 = 0;
                    if (mr > tf32r(m1) && mr > tf32r(m2))
                        e2 = (m > 0.2f) ? 2 : ((m > 0.1f) ? 1 : 0);
                    sbits[l] = __ballot_sync(0xffffffffu, e2 == 2);
                    wbits[l] = __ballot_sync(0xffffffffu, e2 == 1);
                }
                if (lane == 0) {
                    int c0i = 4*p;
                    int base0 = ((b*CC + c0i)*HH + y0 + r)*WPR + blockIdx.x;
                    #pragma unroll
                    for (int l = 0; l < 4; l++) {
                        if (c0i + l < CC) {
                            g_strong[base0 + l*HH*WPR] = sbits[l];
                            g_weak  [base0 + l*HH*WPR] = wbits[l];
                        }
                    }
                }
            }
        }
        __syncthreads();   // protect s_mag (=s_v) from next pass's vblur
    }
}

// ---------------------------------------------------------------------------
// Kernel 2: fused flood (blocks 0..87) + loss-main (blocks 88..599). (R10)
// ---------------------------------------------------------------------------
__global__ void __launch_bounds__(1024) flood_loss_kernel(
    const float* __restrict__ pd,
    const int*   __restrict__ gt,
    const float* __restrict__ weight)
{
    extern __shared__ uint32_t sh[];
    const int tid = threadIdx.x;

    if (blockIdx.x >= NIMG) {
        const int lbid = blockIdx.x - NIMG;
        const int q    = lbid * 1024 + tid;
        const int b    = q >> 16;
        const int hwq  = q & 65535;

        const int4 g4 = ((const int4*)gt)[q];
        const float4* base = (const float4*)pd + (((size_t)b * CC) << 16) + hwq;
        float4 vals[CC];
        #pragma unroll
        for (int c = 0; c < CC; c++) vals[c] = base[(size_t)c << 16];

        float4 tq;
        float acc = 0.f;
        const int gs[4] = {g4.x, g4.y, g4.z, g4.w};
        #pragma unroll
        for (int j = 0; j < 4; j++) {
            int g = gs[j];
            float vmax = -1e30f, vg = 0.f;
            #pragma unroll
            for (int c = 0; c < CC; c++) {
                float v = (j == 0) ? vals[c].x : (j == 1) ? vals[c].y
                        : (j == 2) ? vals[c].z : vals[c].w;
                if (c == g) vg = v;
                vmax = fmaxf(vmax, v);
            }
            float s = 0.f;
            #pragma unroll
            for (int c = 0; c < CC; c++) {
                float v = (j == 0) ? vals[c].x : (j == 1) ? vals[c].y
                        : (j == 2) ? vals[c].z : vals[c].w;
                s += __expf(v - vmax);
            }
            float lse = vmax + __logf(s);
            float t = weight[g] * (vg - lse);
            ((float*)&tq)[j] = t;
            acc += t;
        }
        ((float4*)g_t)[q] = tq;

        #pragma unroll
        for (int off = 16; off > 0; off >>= 1)
            acc += __shfl_down_sync(0xffffffffu, acc, off);
        float* ws = (float*)sh;
        if ((tid & 31) == 0) ws[tid >> 5] = acc;
        __syncthreads();
        if (tid == 0) {
            float t = 0.f;
            #pragma unroll
            for (int i = 0; i < 32; i++) t += ws[i];
            g_p1[lbid] = t;
        }
        return;
    }

    uint32_t* sS = sh;
    uint32_t* sW = sh + WPI;

    const int img = blockIdx.x;
    const uint32_t* gs = g_strong + (size_t)img * WPI;
    const uint32_t* gw = g_weak   + (size_t)img * WPI;

    for (int i = tid; i < WPI; i += 1024) {
        uint32_t s = gs[i];
        sS[i] = s;
        sW[i] = gw[i] & ~s;
    }
    __syncthreads();

    const int col = tid & 15;
    const int r0  = (tid >> 4) * 8;

    for (;;) {
        bool ch = false;
        #pragma unroll
        for (int pass = 0; pass < 2; pass++) {
            for (int kk = 0; kk < 8; kk++) {
                int k = pass ? 7 - kk : kk;
                int r = r0 + k;
                int i = r * WPR + col;
                uint32_t w = sW[i];
                if (!w) continue;
                uint32_t ext = 0;
                if (r > 0)     ext |= sS[i - WPR];
                if (r < HH-1)  ext |= sS[i + WPR];
                uint32_t side = 0;
                if (col > 0) {
                    uint32_t lo = sS[i-1];
                    if (r > 0)    lo |= sS[i-1-WPR];
                    if (r < HH-1) lo |= sS[i-1+WPR];
                    side |= lo >> 31;
                }
                if (col < WPR-1) {
                    uint32_t hi = sS[i+1];
                    if (r > 0)    hi |= sS[i+1-WPR];
                    if (r < HH-1) hi |= sS[i+1+WPR];
                    side |= hi << 31;
                }
                uint32_t cur = sS[i];
                bool lch = false;
                for (;;) {
                    uint32_t o = cur | ext;
                    uint32_t d = o | (o << 1) | (o >> 1) | side;
                    uint32_t cand = d & w;
                    if (!cand) break;
                    cur |= cand; w &= ~cand; lch = true;
                }
                if (lch) { sS[i] = cur; sW[i] = w; ch = true; }
            }
        }
        if (!__syncthreads_or((int)ch)) break;
    }

    uint32_t* gd = g_dil + (size_t)img * WPI;
    #pragma unroll
    for (int k = 0; k < 8; k++) {
        int r = r0 + k;
        int i = r * WPR + col;
        uint32_t s = sS[i];
        uint32_t d = s | (s << 1) | (s >> 1);
        if (r > 0)       d |= sS[i - WPR];
        if (r < HH-1)    d |= sS[i + WPR];
        if (col > 0)     d |= sS[i-1] >> 31;
        if (col < WPR-1) d |= sS[i+1] << 31;
        gd[i] = d;
    }
}

// ---------------------------------------------------------------------------
// Kernel 3: loss edge correction S2 + fused final reduction. (R10)
// ---------------------------------------------------------------------------
__global__ void __launch_bounds__(256) loss_edge_kernel(const int* __restrict__ gt,
                                                        float* __restrict__ out)
{
    const int q  = blockIdx.x * 256 + threadIdx.x;
    const int b  = q >> 16;
    const int hw = (q & 65535) << 2;
    const int widx = hw >> 5;

    const int4   g4 = ((const int4*)gt)[q];
    const float4 t4 = ((const float4*)g_t)[q];

    float s2 = 0.f;
    const int   gs[4] = {g4.x, g4.y, g4.z, g4.w};
    const float ts[4] = {t4.x, t4.y, t4.z, t4.w};
    #pragma unroll
    for (int j = 0; j < 4; j++) {
        uint32_t bits = g_dil[(size_t)(b * CC + gs[j]) * WPI + widx];
        if ((bits >> ((hw + j) & 31)) & 1u) s2 += ts[j];
    }

    #pragma unroll
    for (int off = 16; off > 0; off >>= 1)
        s2 += __shfl_down_sync(0xffffffffu, s2, off);
    __shared__ float ws[8];
    if ((threadIdx.x & 31) == 0) ws[threadIdx.x >> 5] = s2;
    __syncthreads();
    __shared__ bool isLast;
    if (threadIdx.x == 0) {
        float t = 0.f;
        #pragma unroll
        for (int i = 0; i < 8; i++) t += ws[i];
        g_p2[blockIdx.x] = t;
        __threadfence();
        unsigned v = atomicAdd(&g_count, 1u);
        isLast = (v == NLOSS2 - 1);
    }
    __syncthreads();

    if (isLast) {
        __shared__ double red[256];
        double a = 0.0;
        for (int i = threadIdx.x; i < NLOSS1; i += 256) a += (double)g_p1[i];
        for (int i = threadIdx.x; i < NLOSS2; i += 256) a += 2.0 * (double)g_p2[i];
        red[threadIdx.x] = a;
        __syncthreads();
        for (int s = 128; s > 0; s >>= 1) {
            if (threadIdx.x < s) red[threadIdx.x] += red[threadIdx.x + s];
            __syncthreads();
        }
        if (threadIdx.x == 0) {
            out[0] = (float)(-red[0] / 2097152.0);
            g_count = 0;
        }
    }
}

// ---------------------------------------------------------------------------
extern "C" void kernel_launch(void* const* d_in, const int* in_sizes, int n_in,
                              void* d_out, int out_size)
{
    (void)in_sizes; (void)n_in; (void)out_size;
    const float* pd     = (const float*)d_in[0];
    const int*   gt     = (const int*)  d_in[1];
    const float* weight = (const float*)d_in[2];
    float* out = (float*)d_out;

    cudaFuncSetAttribute(flood_loss_kernel,
                         cudaFuncAttributeMaxDynamicSharedMemorySize, 2 * WPI * 4);

    dim3 eg(16, 16, BB);
    edges_kernel<<<eg, 512>>>(gt);
    flood_loss_kernel<<<NIMG + NLOSS1, 1024, 2 * WPI * 4>>>(pd, gt, weight);
    loss_edge_kernel<<<NLOSS2, 256>>>(gt, out);
}